// round 3
// baseline (speedup 1.0000x reference)
#include <cuda_runtime.h>
#include <math.h>
#include <float.h>

// Problem dims
#define BATCH 64
#define NN    10000
#define NC    201
#define H     64
#define ND    128      // node feature dim (2H)
#define FEAT  384      // actor input dim (6H)
#define HA    256      // actor/critic hidden
#define NB    10       // node partial blocks per batch
#define NODES_PER_BLK (NN / NB)
#define TILE  32       // nodes per shared tile in featpool
#define CC    32       // candidates per actor block
#define NCHUNK 7       // ceil(201/32)
#define FS    36       // padded stride for feat smem rows (float4-aligned)
#define MS    36

// Scratch (device globals: no allocation allowed)
__device__ float g_psum[BATCH][NB][ND];
__device__ float g_pmax[BATCH][NB][ND];
__device__ float g_pooled[BATCH][2 * ND];
__device__ float g_scores[BATCH][NC];
__device__ int   g_mask_i32;

// ---------------------------------------------------------------------------
// K0: sniff mask dtype. If the bool mask was stored as int32, every byte at
// offset % 4 != 0 is zero (values are 0/1). If stored as 1-byte bool, those
// offsets carry random 0/1 values, so some are nonzero. Deterministic.
// ---------------------------------------------------------------------------
__global__ void k_sniff(const unsigned char* __restrict__ m) {
    if (threadIdx.x == 0) {
        int any = 0;
        for (int i = 0; i < 1024; i++)
            if ((i & 3) && m[i]) any = 1;
        g_mask_i32 = any ? 0 : 1;
    }
}

// ---------------------------------------------------------------------------
// K1: fused feature-extract + pooling partials.
// Block = 128 threads, thread d owns output feature d and keeps the fe_w2
// column in registers. Nodes stream through shared in tiles of 32.
// ---------------------------------------------------------------------------
__global__ __launch_bounds__(128) void k_featpool(
    const float* __restrict__ x,
    const float* __restrict__ w1, const float* __restrict__ b1,
    const float* __restrict__ w2, const float* __restrict__ b2)
{
    __shared__ float s_w1[3 * H];
    __shared__ float s_b1[H];
    __shared__ float s_x[TILE * 3];
    __shared__ __align__(16) float s_h[TILE * H];

    const int tid = threadIdx.x;
    const int b = blockIdx.y, nb = blockIdx.x;
    const int d = tid;

    float w2r[H];
#pragma unroll
    for (int k = 0; k < H; k++) w2r[k] = w2[k * ND + d];
    const float b2d = b2[d];

    // FIX: 3*H = 192 > blockDim (128); must stride. (Round-1/2 bug: s_w1[128..191]
    // was uninitialized shared memory -> garbage x[2] contribution -> pooled wrong.)
    for (int i = tid; i < 3 * H; i += 128) s_w1[i] = w1[i];
    if (tid < H) s_b1[tid] = b1[tid];
    __syncthreads();

    float sumd = 0.f, maxd = 0.f;  // relu output >= 0, so 0 is a valid max init
    const int start = nb * NODES_PER_BLK, end = start + NODES_PER_BLK;

    for (int t = start; t < end; t += TILE) {
        const int cnt = min(TILE, end - t);
        if (tid < cnt * 3)
            s_x[tid] = x[((long)b * NN + t) * 3 + tid];
        __syncthreads();

        // layer 1: h = relu(x @ w1 + b1), cnt*64 values
        for (int idx = tid; idx < cnt * H; idx += 128) {
            const int n = idx >> 6, k = idx & 63;
            float v = s_b1[k];
            v = fmaf(s_x[n * 3 + 0], s_w1[k],         v);
            v = fmaf(s_x[n * 3 + 1], s_w1[H + k],     v);
            v = fmaf(s_x[n * 3 + 2], s_w1[2 * H + k], v);
            s_h[idx] = fmaxf(v, 0.f);
        }
        __syncthreads();

        // layer 2 + pooling: thread d computes h_nodes[n][d] for every node
        for (int n = 0; n < cnt; n++) {
            const float4* h4 = (const float4*)(s_h + n * H);
            float a0 = 0.f, a1 = 0.f, a2 = 0.f, a3 = 0.f;
#pragma unroll
            for (int q = 0; q < 16; q++) {
                const float4 hv = h4[q];
                a0 = fmaf(hv.x, w2r[4 * q + 0], a0);
                a1 = fmaf(hv.y, w2r[4 * q + 1], a1);
                a2 = fmaf(hv.z, w2r[4 * q + 2], a2);
                a3 = fmaf(hv.w, w2r[4 * q + 3], a3);
            }
            const float y = fmaxf((a0 + a1) + (a2 + a3) + b2d, 0.f);
            sumd += y;
            maxd = fmaxf(maxd, y);
        }
        __syncthreads();
    }
    g_psum[b][nb][d] = sumd;
    g_pmax[b][nb][d] = maxd;
}

// ---------------------------------------------------------------------------
// K1b: combine partials -> pooled [mean || max]
// ---------------------------------------------------------------------------
__global__ void k_pool() {
    const int b = blockIdx.x, d = threadIdx.x;
    float s = 0.f, m = 0.f;
#pragma unroll
    for (int nb = 0; nb < NB; nb++) {
        s += g_psum[b][nb][d];
        m = fmaxf(m, g_pmax[b][nb][d]);
    }
    g_pooled[b][d]      = s * (1.f / NN);
    g_pooled[b][ND + d] = m;
}

// ---------------------------------------------------------------------------
// K2: actor. Block = (batch b, chunk of 32 candidates), 256 threads.
// ---------------------------------------------------------------------------
__global__ __launch_bounds__(256) void k_actor(
    const float* __restrict__ x, const int* __restrict__ cand,
    const float* __restrict__ fw1, const float* __restrict__ fb1,
    const float* __restrict__ fw2, const float* __restrict__ fb2,
    const float* __restrict__ aw1, const float* __restrict__ ab1,
    const float* __restrict__ aw2, const float* __restrict__ ab2,
    const float* __restrict__ aw3, const float* __restrict__ ab3)
{
    extern __shared__ float sm[];
    float* s_feat = sm;                     // FEAT*FS
    float* s_mid  = s_feat + FEAT * FS;     // HA*MS
    float* s_h    = s_mid + HA * MS;        // CC*H
    float* s_x    = s_h + CC * H;           // CC*3
    float* s_red  = s_x + CC * 3;           // 8*CC

    const int tid = threadIdx.x;
    const int b = blockIdx.y;
    const int c0 = blockIdx.x * CC;
    const int nvalid = min(CC, NC - c0);

    // gather candidate x
    if (tid < CC * 3) {
        const int c = tid / 3, i = tid - c * 3;
        float v = 0.f;
        if (c < nvalid) {
            const int node = cand[b * NC + c0 + c];
            v = x[((long)b * NN + node) * 3 + i];
        }
        s_x[tid] = v;
    }
    __syncthreads();

    // candidate h (layer 1)
    for (int idx = tid; idx < CC * H; idx += 256) {
        const int n = idx >> 6, k = idx & 63;
        float v = fb1[k];
        v = fmaf(s_x[n * 3 + 0], fw1[k],         v);
        v = fmaf(s_x[n * 3 + 1], fw1[H + k],     v);
        v = fmaf(s_x[n * 3 + 2], fw1[2 * H + k], v);
        s_h[idx] = fmaxf(v, 0.f);
    }
    __syncthreads();

    // candidate features (layer 2) + pooled rows -> s_feat[i][c]
    {
        const int d = tid & 127;
        const int half = tid >> 7;
        float w2r[H];
#pragma unroll
        for (int k = 0; k < H; k++) w2r[k] = fw2[k * ND + d];
        const float b2d = fb2[d];
        const float pm = g_pooled[b][d];
        const float px = g_pooled[b][ND + d];
        for (int c = half; c < CC; c += 2) {
            const float4* h4 = (const float4*)(s_h + c * H);
            float a0 = 0.f, a1 = 0.f, a2 = 0.f, a3 = 0.f;
#pragma unroll
            for (int q = 0; q < 16; q++) {
                const float4 hv = h4[q];
                a0 = fmaf(hv.x, w2r[4 * q + 0], a0);
                a1 = fmaf(hv.y, w2r[4 * q + 1], a1);
                a2 = fmaf(hv.z, w2r[4 * q + 2], a2);
                a3 = fmaf(hv.w, w2r[4 * q + 3], a3);
            }
            const float y = fmaxf((a0 + a1) + (a2 + a3) + b2d, 0.f);
            s_feat[d * FS + c] = y;
            s_feat[(ND + d) * FS + c]     = pm;
            s_feat[(2 * ND + d) * FS + c] = px;
        }
    }
    __syncthreads();

    const int j = tid;
    float acc[CC];

    // actor layer 1: 384 -> 256 (thread j = output unit, 32 candidates in regs)
#pragma unroll
    for (int c = 0; c < CC; c++) acc[c] = 0.f;
    for (int i = 0; i < FEAT; i++) {
        const float w = __ldg(aw1 + i * HA + j);
        const float4* f4 = (const float4*)(s_feat + i * FS);
#pragma unroll
        for (int q = 0; q < CC / 4; q++) {
            const float4 fv = f4[q];
            acc[4 * q + 0] = fmaf(fv.x, w, acc[4 * q + 0]);
            acc[4 * q + 1] = fmaf(fv.y, w, acc[4 * q + 1]);
            acc[4 * q + 2] = fmaf(fv.z, w, acc[4 * q + 2]);
            acc[4 * q + 3] = fmaf(fv.w, w, acc[4 * q + 3]);
        }
    }
    {
        const float bj = ab1[j];
#pragma unroll
        for (int c = 0; c < CC; c++) s_mid[j * MS + c] = tanhf(acc[c] + bj);
    }
    __syncthreads();

    // actor layer 2: 256 -> 256
#pragma unroll
    for (int c = 0; c < CC; c++) acc[c] = 0.f;
    for (int i = 0; i < HA; i++) {
        const float w = __ldg(aw2 + i * HA + j);
        const float4* f4 = (const float4*)(s_mid + i * MS);
#pragma unroll
        for (int q = 0; q < CC / 4; q++) {
            const float4 fv = f4[q];
            acc[4 * q + 0] = fmaf(fv.x, w, acc[4 * q + 0]);
            acc[4 * q + 1] = fmaf(fv.y, w, acc[4 * q + 1]);
            acc[4 * q + 2] = fmaf(fv.z, w, acc[4 * q + 2]);
            acc[4 * q + 3] = fmaf(fv.w, w, acc[4 * q + 3]);
        }
    }

    // layer 3 (256 -> 1) fused into cross-thread reduction
    const float bj2 = ab2[j];
    const float w3j = aw3[j];
    const int lane = tid & 31, warp = tid >> 5;
#pragma unroll
    for (int c = 0; c < CC; c++) {
        float v = tanhf(acc[c] + bj2) * w3j;
        v += __shfl_xor_sync(0xffffffffu, v, 16);
        v += __shfl_xor_sync(0xffffffffu, v, 8);
        v += __shfl_xor_sync(0xffffffffu, v, 4);
        v += __shfl_xor_sync(0xffffffffu, v, 2);
        v += __shfl_xor_sync(0xffffffffu, v, 1);
        if (lane == 0) s_red[warp * CC + c] = v;
    }
    __syncthreads();
    if (tid < CC) {
        float s = ab3[0];
#pragma unroll
        for (int w = 0; w < 8; w++) s += s_red[w * CC + tid];
        if (tid < nvalid) g_scores[b][c0 + tid] = s;
    }
}

// ---------------------------------------------------------------------------
// K3: critic MLP on pooled feature + masked softmax over candidates.
// ---------------------------------------------------------------------------
__global__ __launch_bounds__(256) void k_final(
    const unsigned char* __restrict__ mask,
    const float* __restrict__ cw1, const float* __restrict__ cb1,
    const float* __restrict__ cw2, const float* __restrict__ cb2,
    const float* __restrict__ cw3, const float* __restrict__ cb3,
    float* __restrict__ out)
{
    __shared__ float s_in[HA];
    __shared__ float s_hid[HA];
    __shared__ float s_r[8];
    __shared__ float s_b0, s_b1v;

    const int tid = threadIdx.x, b = blockIdx.x;
    const int lane = tid & 31, warp = tid >> 5;

    // --- critic ---
    s_in[tid] = g_pooled[b][tid];
    __syncthreads();
    float acc = cb1[tid];
    for (int i = 0; i < HA; i++) acc = fmaf(s_in[i], cw1[i * HA + tid], acc);
    s_hid[tid] = tanhf(acc);
    __syncthreads();
    acc = cb2[tid];
    for (int i = 0; i < HA; i++) acc = fmaf(s_hid[i], cw2[i * HA + tid], acc);
    {
        float p = tanhf(acc) * cw3[tid];
        p += __shfl_xor_sync(0xffffffffu, p, 16);
        p += __shfl_xor_sync(0xffffffffu, p, 8);
        p += __shfl_xor_sync(0xffffffffu, p, 4);
        p += __shfl_xor_sync(0xffffffffu, p, 2);
        p += __shfl_xor_sync(0xffffffffu, p, 1);
        if (lane == 0) s_r[warp] = p;
    }
    __syncthreads();
    if (tid == 0) {
        float v = cb3[0];
#pragma unroll
        for (int w = 0; w < 8; w++) v += s_r[w];
        out[BATCH * NC + b] = v;
    }

    // --- masked softmax over candidates ---
    const int c = tid;
    bool valid = false;
    float s = -FLT_MAX;
    if (c < NC) {
        const int mi = b * NC + c;
        const int mv = g_mask_i32 ? ((const int*)mask)[mi] : (int)mask[mi];
        valid = (mv != 0);
        if (valid) s = g_scores[b][c];
    }
    float m = s;
    m = fmaxf(m, __shfl_xor_sync(0xffffffffu, m, 16));
    m = fmaxf(m, __shfl_xor_sync(0xffffffffu, m, 8));
    m = fmaxf(m, __shfl_xor_sync(0xffffffffu, m, 4));
    m = fmaxf(m, __shfl_xor_sync(0xffffffffu, m, 2));
    m = fmaxf(m, __shfl_xor_sync(0xffffffffu, m, 1));
    __syncthreads();  // s_r reuse (after tid==0 consumed it)
    if (lane == 0) s_r[warp] = m;
    __syncthreads();
    if (warp == 0) {
        float t = (lane < 8) ? s_r[lane] : -FLT_MAX;
        t = fmaxf(t, __shfl_xor_sync(0xffffffffu, t, 4));
        t = fmaxf(t, __shfl_xor_sync(0xffffffffu, t, 2));
        t = fmaxf(t, __shfl_xor_sync(0xffffffffu, t, 1));
        if (lane == 0) s_b0 = t;
    }
    __syncthreads();
    const float mx = s_b0;
    const float e = valid ? expf(s - mx) : 0.f;
    float se = e;
    se += __shfl_xor_sync(0xffffffffu, se, 16);
    se += __shfl_xor_sync(0xffffffffu, se, 8);
    se += __shfl_xor_sync(0xffffffffu, se, 4);
    se += __shfl_xor_sync(0xffffffffu, se, 2);
    se += __shfl_xor_sync(0xffffffffu, se, 1);
    __syncthreads();
    if (lane == 0) s_r[warp] = se;
    __syncthreads();
    if (warp == 0) {
        float t = (lane < 8) ? s_r[lane] : 0.f;
        t += __shfl_xor_sync(0xffffffffu, t, 4);
        t += __shfl_xor_sync(0xffffffffu, t, 2);
        t += __shfl_xor_sync(0xffffffffu, t, 1);
        if (lane == 0) s_b1v = t;
    }
    __syncthreads();
    if (c < NC) out[b * NC + c] = e / s_b1v;
}

// ---------------------------------------------------------------------------
extern "C" void kernel_launch(void* const* d_in, const int* in_sizes, int n_in,
                              void* d_out, int out_size)
{
    const float* x    = (const float*)d_in[0];
    const int*   cand = (const int*)d_in[1];
    const unsigned char* mask = (const unsigned char*)d_in[2];
    const float* fw1 = (const float*)d_in[3];
    const float* fb1 = (const float*)d_in[4];
    const float* fw2 = (const float*)d_in[5];
    const float* fb2 = (const float*)d_in[6];
    const float* aw1 = (const float*)d_in[7];
    const float* ab1 = (const float*)d_in[8];
    const float* aw2 = (const float*)d_in[9];
    const float* ab2 = (const float*)d_in[10];
    const float* aw3 = (const float*)d_in[11];
    const float* ab3 = (const float*)d_in[12];
    const float* cw1 = (const float*)d_in[13];
    const float* cb1 = (const float*)d_in[14];
    const float* cw2 = (const float*)d_in[15];
    const float* cb2 = (const float*)d_in[16];
    const float* cw3 = (const float*)d_in[17];
    const float* cb3 = (const float*)d_in[18];
    float* out = (float*)d_out;

    const int smem_actor =
        (FEAT * FS + HA * MS + CC * H + CC * 3 + 8 * CC) * (int)sizeof(float);
    cudaFuncSetAttribute(k_actor, cudaFuncAttributeMaxDynamicSharedMemorySize,
                         smem_actor);

    k_sniff<<<1, 32>>>(mask);
    k_featpool<<<dim3(NB, BATCH), 128>>>(x, fw1, fb1, fw2, fb2);
    k_pool<<<BATCH, ND>>>();
    k_actor<<<dim3(NCHUNK, BATCH), 256, smem_actor>>>(
        x, cand, fw1, fb1, fw2, fb2, aw1, ab1, aw2, ab2, aw3, ab3);
    k_final<<<BATCH, 256>>>(mask, cw1, cb1, cw2, cb2, cw3, cb3, out);
}

// round 4
// speedup vs baseline: 1.3220x; 1.3220x over previous
#include <cuda_runtime.h>
#include <math.h>
#include <float.h>

// Problem dims
#define BATCH 64
#define NN    10000
#define NC    201
#define H     64
#define ND    128      // node feature dim (2H)
#define FEAT  384      // actor input dim (6H)
#define HA    256      // actor/critic hidden
#define NB    9        // node partial blocks per batch
#define NPB   1112     // ceil(NN/NB)
#define TILE  32       // nodes per shared tile in featpool
#define CC    32       // candidates per actor block
#define NCHUNK 7       // ceil(201/32)
#define FS    36       // padded stride (16B-aligned rows: 36*4=144)
#define MS    36

// Scratch (device globals: no allocation allowed)
__device__ float g_psum[BATCH][NB][ND];
__device__ float g_pmax[BATCH][NB][ND];
__device__ float g_pooled[BATCH][2 * ND];
__device__ float g_pproj[BATCH][HA];    // aw1-projection of pooled (const over candidates)
__device__ float g_scores[BATCH][NC];
__device__ int   g_mask_i32;

// ---- f32x2 packed helpers (sm_103a; 2x FMA throughput per inst) ----
static __device__ __forceinline__ unsigned long long dup2(float w) {
    unsigned long long r;
    unsigned int b = __float_as_uint(w);
    asm("mov.b64 %0, {%1, %1};" : "=l"(r) : "r"(b));
    return r;
}
static __device__ __forceinline__ unsigned long long fma2(
    unsigned long long a, unsigned long long b, unsigned long long c) {
    unsigned long long d;
    asm("fma.rn.f32x2 %0, %1, %2, %3;" : "=l"(d) : "l"(a), "l"(b), "l"(c));
    return d;
}
static __device__ __forceinline__ void unpack2(unsigned long long v, float& lo, float& hi) {
    unsigned int a, b;
    asm("mov.b64 {%0, %1}, %2;" : "=r"(a), "=r"(b) : "l"(v));
    lo = __uint_as_float(a);
    hi = __uint_as_float(b);
}

// ---------------------------------------------------------------------------
// K0: sniff mask dtype. int32 storage of 0/1 => bytes at offset%4!=0 all zero.
// ---------------------------------------------------------------------------
__global__ void k_sniff(const unsigned char* __restrict__ m) {
    if (threadIdx.x == 0) {
        int any = 0;
        for (int i = 0; i < 1024; i++)
            if ((i & 3) && m[i]) any = 1;
        g_mask_i32 = any ? 0 : 1;
    }
}

// ---------------------------------------------------------------------------
// K1: fused feature-extract + pooling partials (f32x2 layer 2).
// Thread d owns output feature d. Hidden tile stored TRANSPOSED (s_hT[k][n])
// so one 16B LDS yields two node-pairs for packed FMA.
// ---------------------------------------------------------------------------
__global__ __launch_bounds__(128) void k_featpool(
    const float* __restrict__ x,
    const float* __restrict__ w1, const float* __restrict__ b1,
    const float* __restrict__ w2, const float* __restrict__ b2)
{
    __shared__ float s_w1[3 * H];
    __shared__ float s_b1[H];
    __shared__ float s_x[TILE * 3];
    __shared__ __align__(16) float s_hT[H][TILE];   // transposed hidden tile
    __shared__ float s_w2[H * ND];                  // fe_w2 (identity copy)

    const int tid = threadIdx.x;
    const int b = blockIdx.y, nb = blockIdx.x;

    for (int i = tid; i < 3 * H; i += 128) s_w1[i] = w1[i];
    if (tid < H) s_b1[tid] = b1[tid];
    for (int i = tid; i < H * ND; i += 128) s_w2[i] = w2[i];
    __syncthreads();

    const float b2d = b2[tid];
    float sumd = 0.f, maxd = 0.f;   // relu >= 0, so 0 valid max init
    const int start = nb * NPB;
    const int end = min(start + NPB, NN);

    for (int t = start; t < end; t += TILE) {
        const int cnt = min(TILE, end - t);
        if (tid < TILE * 3) {
            const int n = tid / 3, jj = tid - n * 3;
            s_x[tid] = (n < cnt) ? x[((long)b * NN + t + n) * 3 + jj] : 0.f;
        }
        __syncthreads();

        // layer 1: write transposed. idx -> n=idx&31, k=idx>>5 (full 32-node pad)
#pragma unroll
        for (int m = 0; m < 16; m++) {
            const int idx = m * 128 + tid;
            const int n = idx & 31, k = idx >> 5;
            float v = s_b1[k];
            v = fmaf(s_x[n * 3 + 0], s_w1[k],         v);
            v = fmaf(s_x[n * 3 + 1], s_w1[H + k],     v);
            v = fmaf(s_x[n * 3 + 2], s_w1[2 * H + k], v);
            s_hT[k][n] = fmaxf(v, 0.f);
        }
        __syncthreads();

        // layer 2, packed: acc2[p] accumulates node-pair (2p, 2p+1)
        unsigned long long acc2[16];
#pragma unroll
        for (int p = 0; p < 16; p++) acc2[p] = 0ull;
#pragma unroll 4
        for (int k = 0; k < H; k++) {
            const unsigned long long wd = dup2(s_w2[k * ND + tid]);
            const ulonglong2* row = (const ulonglong2*)(&s_hT[k][0]);
#pragma unroll
            for (int q = 0; q < 8; q++) {
                const ulonglong2 h2 = row[q];
                acc2[2 * q]     = fma2(h2.x, wd, acc2[2 * q]);
                acc2[2 * q + 1] = fma2(h2.y, wd, acc2[2 * q + 1]);
            }
        }
        // epilogue: bias + relu + pool (only valid nodes)
#pragma unroll
        for (int p = 0; p < 16; p++) {
            float lo, hi;
            unpack2(acc2[p], lo, hi);
            if (2 * p < cnt) {
                const float y = fmaxf(lo + b2d, 0.f);
                sumd += y; maxd = fmaxf(maxd, y);
            }
            if (2 * p + 1 < cnt) {
                const float y = fmaxf(hi + b2d, 0.f);
                sumd += y; maxd = fmaxf(maxd, y);
            }
        }
        // no extra sync needed: next iter's sync-after-s_x-write orders s_hT reuse
    }
    g_psum[b][nb][tid] = sumd;
    g_pmax[b][nb][tid] = maxd;
}

// ---------------------------------------------------------------------------
// K1b: combine partials -> pooled; also precompute aw1-projection of pooled
// (constant over candidates => hoisted out of k_actor's layer 1).
// ---------------------------------------------------------------------------
__global__ __launch_bounds__(HA) void k_pool(const float* __restrict__ aw1) {
    __shared__ float s_pool[2 * ND];
    const int b = blockIdx.x, tid = threadIdx.x;
    if (tid < ND) {
        float s = 0.f, m = 0.f;
#pragma unroll
        for (int nb = 0; nb < NB; nb++) {
            s += g_psum[b][nb][tid];
            m = fmaxf(m, g_pmax[b][nb][tid]);
        }
        const float mean = s * (1.f / NN);
        g_pooled[b][tid] = mean;
        g_pooled[b][ND + tid] = m;
        s_pool[tid] = mean;
        s_pool[ND + tid] = m;
    }
    __syncthreads();
    float pc = 0.f;
    for (int i = 0; i < 2 * ND; i++)
        pc = fmaf(s_pool[i], __ldg(aw1 + (ND + i) * HA + tid), pc);
    g_pproj[b][tid] = pc;
}

// ---------------------------------------------------------------------------
// K2: actor. s_feat holds only the 128 candidate-feature rows (pooled part
// folded into g_pproj). Both dense layers use f32x2. smem ~65KB -> 2 CTAs/SM.
// ---------------------------------------------------------------------------
__global__ __launch_bounds__(256) void k_actor(
    const float* __restrict__ x, const int* __restrict__ cand,
    const float* __restrict__ fw1, const float* __restrict__ fb1,
    const float* __restrict__ fw2, const float* __restrict__ fb2,
    const float* __restrict__ aw1, const float* __restrict__ ab1,
    const float* __restrict__ aw2, const float* __restrict__ ab2,
    const float* __restrict__ aw3, const float* __restrict__ ab3)
{
    extern __shared__ float sm[];
    float* s_feat = sm;                     // ND*FS   (128 rows x 32 cands)
    float* s_mid  = s_feat + ND * FS;       // HA*MS
    float* s_h    = s_mid + HA * MS;        // CC*H
    float* s_x    = s_h + CC * H;           // CC*3
    float* s_red  = s_x + CC * 3;           // 8*CC

    const int tid = threadIdx.x;
    const int b = blockIdx.y;
    const int c0 = blockIdx.x * CC;
    const int nvalid = min(CC, NC - c0);

    // gather candidate x
    if (tid < CC * 3) {
        const int c = tid / 3, i = tid - c * 3;
        float v = 0.f;
        if (c < nvalid) {
            const int node = cand[b * NC + c0 + c];
            v = x[((long)b * NN + node) * 3 + i];
        }
        s_x[tid] = v;
    }
    __syncthreads();

    // candidate hidden (fe layer 1)
    for (int idx = tid; idx < CC * H; idx += 256) {
        const int n = idx >> 6, k = idx & 63;
        float v = fb1[k];
        v = fmaf(s_x[n * 3 + 0], fw1[k],         v);
        v = fmaf(s_x[n * 3 + 1], fw1[H + k],     v);
        v = fmaf(s_x[n * 3 + 2], fw1[2 * H + k], v);
        s_h[idx] = fmaxf(v, 0.f);
    }
    __syncthreads();

    // candidate features (fe layer 2) -> s_feat[d][c]
    {
        const int d = tid & 127;
        const int half = tid >> 7;
        float w2r[H];
#pragma unroll
        for (int k = 0; k < H; k++) w2r[k] = fw2[k * ND + d];
        const float b2d = fb2[d];
        for (int c = half; c < CC; c += 2) {
            const float4* h4 = (const float4*)(s_h + c * H);
            float a0 = 0.f, a1 = 0.f, a2 = 0.f, a3 = 0.f;
#pragma unroll
            for (int q = 0; q < 16; q++) {
                const float4 hv = h4[q];
                a0 = fmaf(hv.x, w2r[4 * q + 0], a0);
                a1 = fmaf(hv.y, w2r[4 * q + 1], a1);
                a2 = fmaf(hv.z, w2r[4 * q + 2], a2);
                a3 = fmaf(hv.w, w2r[4 * q + 3], a3);
            }
            s_feat[d * FS + c] = fmaxf((a0 + a1) + (a2 + a3) + b2d, 0.f);
        }
    }
    __syncthreads();

    const int j = tid;
    const float pc = g_pproj[b][j];
    unsigned long long acc2[16];

    // actor layer 1: 128 cand rows only (pooled part is pc), packed
#pragma unroll
    for (int p = 0; p < 16; p++) acc2[p] = 0ull;
#pragma unroll 4
    for (int i = 0; i < ND; i++) {
        const unsigned long long wd = dup2(__ldg(aw1 + i * HA + j));
        const ulonglong2* row = (const ulonglong2*)(s_feat + i * FS);
#pragma unroll
        for (int q = 0; q < 8; q++) {
            const ulonglong2 f2 = row[q];
            acc2[2 * q]     = fma2(f2.x, wd, acc2[2 * q]);
            acc2[2 * q + 1] = fma2(f2.y, wd, acc2[2 * q + 1]);
        }
    }
    {
        const float bj = ab1[j] + pc;
#pragma unroll
        for (int p = 0; p < 16; p++) {
            float lo, hi;
            unpack2(acc2[p], lo, hi);
            s_mid[j * MS + 2 * p]     = tanhf(lo + bj);
            s_mid[j * MS + 2 * p + 1] = tanhf(hi + bj);
        }
    }
    __syncthreads();

    // actor layer 2: 256 -> 256, packed
#pragma unroll
    for (int p = 0; p < 16; p++) acc2[p] = 0ull;
#pragma unroll 4
    for (int i = 0; i < HA; i++) {
        const unsigned long long wd = dup2(__ldg(aw2 + i * HA + j));
        const ulonglong2* row = (const ulonglong2*)(s_mid + i * MS);
#pragma unroll
        for (int q = 0; q < 8; q++) {
            const ulonglong2 f2 = row[q];
            acc2[2 * q]     = fma2(f2.x, wd, acc2[2 * q]);
            acc2[2 * q + 1] = fma2(f2.y, wd, acc2[2 * q + 1]);
        }
    }

    // layer 3 (256 -> 1) fused into cross-thread reduction
    const float bj2 = ab2[j];
    const float w3j = aw3[j];
    const int lane = tid & 31, warp = tid >> 5;
#pragma unroll
    for (int p = 0; p < 16; p++) {
        float lo, hi;
        unpack2(acc2[p], lo, hi);
        float v0 = tanhf(lo + bj2) * w3j;
        float v1 = tanhf(hi + bj2) * w3j;
        v0 += __shfl_xor_sync(0xffffffffu, v0, 16);
        v0 += __shfl_xor_sync(0xffffffffu, v0, 8);
        v0 += __shfl_xor_sync(0xffffffffu, v0, 4);
        v0 += __shfl_xor_sync(0xffffffffu, v0, 2);
        v0 += __shfl_xor_sync(0xffffffffu, v0, 1);
        v1 += __shfl_xor_sync(0xffffffffu, v1, 16);
        v1 += __shfl_xor_sync(0xffffffffu, v1, 8);
        v1 += __shfl_xor_sync(0xffffffffu, v1, 4);
        v1 += __shfl_xor_sync(0xffffffffu, v1, 2);
        v1 += __shfl_xor_sync(0xffffffffu, v1, 1);
        if (lane == 0) {
            s_red[warp * CC + 2 * p]     = v0;
            s_red[warp * CC + 2 * p + 1] = v1;
        }
    }
    __syncthreads();
    if (tid < CC) {
        float s = ab3[0];
#pragma unroll
        for (int w = 0; w < 8; w++) s += s_red[w * CC + tid];
        if (tid < nvalid) g_scores[b][c0 + tid] = s;
    }
}

// ---------------------------------------------------------------------------
// K3: critic MLP on pooled feature + masked softmax over candidates.
// ---------------------------------------------------------------------------
__global__ __launch_bounds__(256) void k_final(
    const unsigned char* __restrict__ mask,
    const float* __restrict__ cw1, const float* __restrict__ cb1,
    const float* __restrict__ cw2, const float* __restrict__ cb2,
    const float* __restrict__ cw3, const float* __restrict__ cb3,
    float* __restrict__ out)
{
    __shared__ float s_in[HA];
    __shared__ float s_hid[HA];
    __shared__ float s_r[8];
    __shared__ float s_b0, s_b1v;

    const int tid = threadIdx.x, b = blockIdx.x;
    const int lane = tid & 31, warp = tid >> 5;

    // --- critic ---
    s_in[tid] = g_pooled[b][tid];
    __syncthreads();
    float acc = cb1[tid];
    for (int i = 0; i < HA; i++) acc = fmaf(s_in[i], cw1[i * HA + tid], acc);
    s_hid[tid] = tanhf(acc);
    __syncthreads();
    acc = cb2[tid];
    for (int i = 0; i < HA; i++) acc = fmaf(s_hid[i], cw2[i * HA + tid], acc);
    {
        float p = tanhf(acc) * cw3[tid];
        p += __shfl_xor_sync(0xffffffffu, p, 16);
        p += __shfl_xor_sync(0xffffffffu, p, 8);
        p += __shfl_xor_sync(0xffffffffu, p, 4);
        p += __shfl_xor_sync(0xffffffffu, p, 2);
        p += __shfl_xor_sync(0xffffffffu, p, 1);
        if (lane == 0) s_r[warp] = p;
    }
    __syncthreads();
    if (tid == 0) {
        float v = cb3[0];
#pragma unroll
        for (int w = 0; w < 8; w++) v += s_r[w];
        out[BATCH * NC + b] = v;
    }

    // --- masked softmax over candidates ---
    const int c = tid;
    bool valid = false;
    float s = -FLT_MAX;
    if (c < NC) {
        const int mi = b * NC + c;
        const int mv = g_mask_i32 ? ((const int*)mask)[mi] : (int)mask[mi];
        valid = (mv != 0);
        if (valid) s = g_scores[b][c];
    }
    float m = s;
    m = fmaxf(m, __shfl_xor_sync(0xffffffffu, m, 16));
    m = fmaxf(m, __shfl_xor_sync(0xffffffffu, m, 8));
    m = fmaxf(m, __shfl_xor_sync(0xffffffffu, m, 4));
    m = fmaxf(m, __shfl_xor_sync(0xffffffffu, m, 2));
    m = fmaxf(m, __shfl_xor_sync(0xffffffffu, m, 1));
    __syncthreads();
    if (lane == 0) s_r[warp] = m;
    __syncthreads();
    if (warp == 0) {
        float t = (lane < 8) ? s_r[lane] : -FLT_MAX;
        t = fmaxf(t, __shfl_xor_sync(0xffffffffu, t, 4));
        t = fmaxf(t, __shfl_xor_sync(0xffffffffu, t, 2));
        t = fmaxf(t, __shfl_xor_sync(0xffffffffu, t, 1));
        if (lane == 0) s_b0 = t;
    }
    __syncthreads();
    const float mx = s_b0;
    const float e = valid ? expf(s - mx) : 0.f;
    float se = e;
    se += __shfl_xor_sync(0xffffffffu, se, 16);
    se += __shfl_xor_sync(0xffffffffu, se, 8);
    se += __shfl_xor_sync(0xffffffffu, se, 4);
    se += __shfl_xor_sync(0xffffffffu, se, 2);
    se += __shfl_xor_sync(0xffffffffu, se, 1);
    __syncthreads();
    if (lane == 0) s_r[warp] = se;
    __syncthreads();
    if (warp == 0) {
        float t = (lane < 8) ? s_r[lane] : 0.f;
        t += __shfl_xor_sync(0xffffffffu, t, 4);
        t += __shfl_xor_sync(0xffffffffu, t, 2);
        t += __shfl_xor_sync(0xffffffffu, t, 1);
        if (lane == 0) s_b1v = t;
    }
    __syncthreads();
    if (c < NC) out[b * NC + c] = e / s_b1v;
}

// ---------------------------------------------------------------------------
extern "C" void kernel_launch(void* const* d_in, const int* in_sizes, int n_in,
                              void* d_out, int out_size)
{
    const float* x    = (const float*)d_in[0];
    const int*   cand = (const int*)d_in[1];
    const unsigned char* mask = (const unsigned char*)d_in[2];
    const float* fw1 = (const float*)d_in[3];
    const float* fb1 = (const float*)d_in[4];
    const float* fw2 = (const float*)d_in[5];
    const float* fb2 = (const float*)d_in[6];
    const float* aw1 = (const float*)d_in[7];
    const float* ab1 = (const float*)d_in[8];
    const float* aw2 = (const float*)d_in[9];
    const float* ab2 = (const float*)d_in[10];
    const float* aw3 = (const float*)d_in[11];
    const float* ab3 = (const float*)d_in[12];
    const float* cw1 = (const float*)d_in[13];
    const float* cb1 = (const float*)d_in[14];
    const float* cw2 = (const float*)d_in[15];
    const float* cb2 = (const float*)d_in[16];
    const float* cw3 = (const float*)d_in[17];
    const float* cb3 = (const float*)d_in[18];
    float* out = (float*)d_out;

    const int smem_actor =
        (ND * FS + HA * MS + CC * H + CC * 3 + 8 * CC) * (int)sizeof(float);
    cudaFuncSetAttribute(k_actor, cudaFuncAttributeMaxDynamicSharedMemorySize,
                         smem_actor);

    k_sniff<<<1, 32>>>(mask);
    k_featpool<<<dim3(NB, BATCH), 128>>>(x, fw1, fb1, fw2, fb2);
    k_pool<<<BATCH, HA>>>(aw1);
    k_actor<<<dim3(NCHUNK, BATCH), 256, smem_actor>>>(
        x, cand, fw1, fb1, fw2, fb2, aw1, ab1, aw2, ab2, aw3, ab3);
    k_final<<<BATCH, 256>>>(mask, cw1, cb1, cw2, cb2, cw3, cb3, out);
}

// round 5
// speedup vs baseline: 1.8443x; 1.3951x over previous
#include <cuda_runtime.h>
#include <math.h>
#include <float.h>

// Problem dims
#define BATCH 64
#define NN    10000
#define NC    201
#define H     64
#define ND    128      // node feature dim (2H)
#define HA    256      // actor/critic hidden
#define NB    9        // node partial blocks per batch
#define NPB   1112     // ceil(NN/NB)
#define TILE  32       // nodes per shared tile in featpool
#define CC    32       // candidates per actor block
#define NCHUNK 7       // ceil(201/32)
#define FS    36       // padded stride for feat rows (16B multiple)
#define MS    36

// Scratch (device globals: no allocation allowed)
__device__ float g_psum[BATCH][NB][ND];
__device__ float g_pmax[BATCH][NB][ND];
__device__ float g_pooled[BATCH][2 * ND];
__device__ float g_pproj[BATCH][HA];    // aw1-projection of pooled (const over candidates)
__device__ float g_scores[BATCH][NC];
__device__ int   g_mask_i32;

// ---- f32x2 packed helpers ----
static __device__ __forceinline__ unsigned long long dup2(float w) {
    unsigned long long r;
    unsigned int b = __float_as_uint(w);
    asm("mov.b64 %0, {%1, %1};" : "=l"(r) : "r"(b));
    return r;
}
static __device__ __forceinline__ unsigned long long fma2(
    unsigned long long a, unsigned long long b, unsigned long long c) {
    unsigned long long d;
    asm("fma.rn.f32x2 %0, %1, %2, %3;" : "=l"(d) : "l"(a), "l"(b), "l"(c));
    return d;
}
static __device__ __forceinline__ void unpack2(unsigned long long v, float& lo, float& hi) {
    unsigned int a, b;
    asm("mov.b64 {%0, %1}, %2;" : "=r"(a), "=r"(b) : "l"(v));
    lo = __uint_as_float(a);
    hi = __uint_as_float(b);
}

// ---------------------------------------------------------------------------
// K0: sniff mask dtype. int32 storage of 0/1 => bytes at offset%4!=0 all zero.
// ---------------------------------------------------------------------------
__global__ void k_sniff(const unsigned char* __restrict__ m) {
    if (threadIdx.x == 0) {
        int any = 0;
        for (int i = 0; i < 1024; i++)
            if ((i & 3) && m[i]) any = 1;
        g_mask_i32 = any ? 0 : 1;
    }
}

// ---------------------------------------------------------------------------
// K1: fused feature-extract + pooling partials.
// Layer 1: thread = (node n1, k-group): w1 via one LDS.128, x in registers.
// Layer 2: thread = (2 d-columns dg, node-half ph): per k only
//          4 LDS.128 (h) + 1 LDS.64 (w-pair) + 2 dup for 32 FFMA2.
// ---------------------------------------------------------------------------
__global__ __launch_bounds__(128) void k_featpool(
    const float* __restrict__ x,
    const float* __restrict__ w1, const float* __restrict__ b1,
    const float* __restrict__ w2, const float* __restrict__ b2)
{
    __shared__ __align__(16) float s_w1t[H][4];     // [k][w0,w1,w2,b1]
    __shared__ float s_x[TILE * 3];
    __shared__ __align__(16) float s_hT[H][TILE];   // hidden, transposed
    __shared__ __align__(16) float s_w2[H * ND];

    const int tid = threadIdx.x;
    const int b = blockIdx.y, nb = blockIdx.x;

    if (tid < H) {
        s_w1t[tid][0] = w1[tid];
        s_w1t[tid][1] = w1[H + tid];
        s_w1t[tid][2] = w1[2 * H + tid];
        s_w1t[tid][3] = b1[tid];
    }
    for (int i = tid; i < H * ND; i += 128) s_w2[i] = w2[i];

    // layer-1 role
    const int n1 = tid & 31, kg = tid >> 5;
    // layer-2 role: 2 d-columns, 16-node half
    const int dg = tid >> 1, ph = tid & 1;
    const int d0 = 2 * dg, d1 = d0 + 1;
    const float b20 = b2[d0], b21 = b2[d1];

    float sum0 = 0.f, sum1 = 0.f, max0 = 0.f, max1 = 0.f;  // relu >= 0
    const int start = nb * NPB;
    const int end = min(start + NPB, NN);

    for (int t = start; t < end; t += TILE) {
        const int cnt = min(TILE, end - t);
        if (tid < TILE * 3) {
            const int n = tid / 3, jj = tid - n * 3;
            s_x[tid] = (n < cnt) ? x[((long)b * NN + t + n) * 3 + jj] : 0.f;
        }
        __syncthreads();

        // layer 1: thread computes h[k][n1] for k = kg*16 .. kg*16+15
        {
            const float x0 = s_x[n1 * 3 + 0];
            const float x1 = s_x[n1 * 3 + 1];
            const float x2 = s_x[n1 * 3 + 2];
#pragma unroll
            for (int m = 0; m < 16; m++) {
                const int k = kg * 16 + m;
                const float4 w = *(const float4*)&s_w1t[k][0];
                const float v = fmaf(x0, w.x, fmaf(x1, w.y, fmaf(x2, w.z, w.w)));
                s_hT[k][n1] = fmaxf(v, 0.f);
            }
        }
        __syncthreads();

        // layer 2, packed: acc[4q+0]=d0/nodes(4q,4q+1), [4q+1]=d1/same,
        //                  [4q+2]=d0/nodes(4q+2,4q+3), [4q+3]=d1/same
        unsigned long long a2[16];
#pragma unroll
        for (int p = 0; p < 16; p++) a2[p] = 0ull;
#pragma unroll 4
        for (int k = 0; k < H; k++) {
            const float2 wp = *(const float2*)&s_w2[k * ND + d0];
            const unsigned long long w0 = dup2(wp.x);
            const unsigned long long w1d = dup2(wp.y);
            const ulonglong2* row = (const ulonglong2*)&s_hT[k][ph * 16];
#pragma unroll
            for (int q = 0; q < 4; q++) {
                const ulonglong2 h2 = row[q];
                a2[4 * q + 0] = fma2(h2.x, w0,  a2[4 * q + 0]);
                a2[4 * q + 1] = fma2(h2.x, w1d, a2[4 * q + 1]);
                a2[4 * q + 2] = fma2(h2.y, w0,  a2[4 * q + 2]);
                a2[4 * q + 3] = fma2(h2.y, w1d, a2[4 * q + 3]);
            }
        }
        // epilogue: bias + relu + pool, node-guarded
#pragma unroll
        for (int q = 0; q < 4; q++) {
            const int nb0 = ph * 16 + 4 * q;  // node of first lane of h2.x
            float lo, hi;
            unpack2(a2[4 * q + 0], lo, hi);
            if (nb0 < cnt)     { const float y = fmaxf(lo + b20, 0.f); sum0 += y; max0 = fmaxf(max0, y); }
            if (nb0 + 1 < cnt) { const float y = fmaxf(hi + b20, 0.f); sum0 += y; max0 = fmaxf(max0, y); }
            unpack2(a2[4 * q + 1], lo, hi);
            if (nb0 < cnt)     { const float y = fmaxf(lo + b21, 0.f); sum1 += y; max1 = fmaxf(max1, y); }
            if (nb0 + 1 < cnt) { const float y = fmaxf(hi + b21, 0.f); sum1 += y; max1 = fmaxf(max1, y); }
            unpack2(a2[4 * q + 2], lo, hi);
            if (nb0 + 2 < cnt) { const float y = fmaxf(lo + b20, 0.f); sum0 += y; max0 = fmaxf(max0, y); }
            if (nb0 + 3 < cnt) { const float y = fmaxf(hi + b20, 0.f); sum0 += y; max0 = fmaxf(max0, y); }
            unpack2(a2[4 * q + 3], lo, hi);
            if (nb0 + 2 < cnt) { const float y = fmaxf(lo + b21, 0.f); sum1 += y; max1 = fmaxf(max1, y); }
            if (nb0 + 3 < cnt) { const float y = fmaxf(hi + b21, 0.f); sum1 += y; max1 = fmaxf(max1, y); }
        }
        // next iteration's post-s_x barrier orders s_hT reuse
    }

    // combine the two node-halves (ph=0/1) per d-pair via s_hT overlay
    __syncthreads();
    float* r = &s_hT[0][0];
    if (ph == 1) {
        r[dg] = sum0; r[64 + dg] = sum1;
        r[128 + dg] = max0; r[192 + dg] = max1;
    }
    __syncthreads();
    if (ph == 0) {
        sum0 += r[dg]; sum1 += r[64 + dg];
        max0 = fmaxf(max0, r[128 + dg]); max1 = fmaxf(max1, r[192 + dg]);
        g_psum[b][nb][d0] = sum0; g_psum[b][nb][d1] = sum1;
        g_pmax[b][nb][d0] = max0; g_pmax[b][nb][d1] = max1;
    }
}

// ---------------------------------------------------------------------------
// K1b: combine partials -> pooled; precompute aw1-projection of pooled.
// ---------------------------------------------------------------------------
__global__ __launch_bounds__(HA) void k_pool(const float* __restrict__ aw1) {
    __shared__ float s_pool[2 * ND];
    const int b = blockIdx.x, tid = threadIdx.x;
    if (tid < ND) {
        float s = 0.f, m = 0.f;
#pragma unroll
        for (int nb = 0; nb < NB; nb++) {
            s += g_psum[b][nb][tid];
            m = fmaxf(m, g_pmax[b][nb][tid]);
        }
        const float mean = s * (1.f / NN);
        g_pooled[b][tid] = mean;
        g_pooled[b][ND + tid] = m;
        s_pool[tid] = mean;
        s_pool[ND + tid] = m;
    }
    __syncthreads();
    float pc = 0.f;
    for (int i = 0; i < 2 * ND; i++)
        pc = fmaf(s_pool[i], __ldg(aw1 + (ND + i) * HA + tid), pc);
    g_pproj[b][tid] = pc;
}

// ---------------------------------------------------------------------------
// K2: actor. 128 threads; thread owns output units j and j+128 so every
// broadcast row load feeds 32 FFMA2. smem ~65KB -> 3 CTAs/SM.
// ---------------------------------------------------------------------------
__global__ __launch_bounds__(128) void k_actor(
    const float* __restrict__ x, const int* __restrict__ cand,
    const float* __restrict__ fw1, const float* __restrict__ fb1,
    const float* __restrict__ fw2, const float* __restrict__ fb2,
    const float* __restrict__ aw1, const float* __restrict__ ab1,
    const float* __restrict__ aw2, const float* __restrict__ ab2,
    const float* __restrict__ aw3, const float* __restrict__ ab3)
{
    extern __shared__ float sm[];
    float* s_feat = sm;                      // ND*FS
    float* s_mid  = s_feat + ND * FS;        // HA*MS
    float* s_hT   = s_mid + HA * MS;         // H*CC
    float* s_x    = s_hT + H * CC;           // CC*3
    float* s_w1t  = s_x + CC * 3;            // H*4
    float* s_red  = s_w1t + H * 4;           // 4*CC

    const int tid = threadIdx.x;
    const int b = blockIdx.y;
    const int c0 = blockIdx.x * CC;
    const int nvalid = min(CC, NC - c0);

    if (tid < H) {
        s_w1t[tid * 4 + 0] = fw1[tid];
        s_w1t[tid * 4 + 1] = fw1[H + tid];
        s_w1t[tid * 4 + 2] = fw1[2 * H + tid];
        s_w1t[tid * 4 + 3] = fb1[tid];
    }
    if (tid < CC * 3) {
        const int c = tid / 3, i = tid - c * 3;
        float v = 0.f;
        if (c < nvalid) {
            const int node = cand[b * NC + c0 + c];
            v = x[((long)b * NN + node) * 3 + i];
        }
        s_x[tid] = v;
    }
    __syncthreads();

    // fe layer 1 -> s_hT[k][c] (transposed)
    {
        const int n1 = tid & 31, kg = tid >> 5;
        const float x0 = s_x[n1 * 3 + 0];
        const float x1 = s_x[n1 * 3 + 1];
        const float x2 = s_x[n1 * 3 + 2];
#pragma unroll
        for (int m = 0; m < 16; m++) {
            const int k = kg * 16 + m;
            const float4 w = *(const float4*)&s_w1t[k * 4];
            const float v = fmaf(x0, w.x, fmaf(x1, w.y, fmaf(x2, w.z, w.w)));
            s_hT[k * CC + n1] = fmaxf(v, 0.f);
        }
    }
    __syncthreads();

    // fe layer 2: thread = (2 d-columns, 16-cand half) -> s_feat[d][c]
    {
        const int dg = tid >> 1, ph = tid & 1;
        const int d0 = 2 * dg, d1 = d0 + 1;
        unsigned long long a2[16];
#pragma unroll
        for (int p = 0; p < 16; p++) a2[p] = 0ull;
#pragma unroll 4
        for (int k = 0; k < H; k++) {
            const float2 wp = __ldg((const float2*)(fw2 + k * ND + d0));
            const unsigned long long w0 = dup2(wp.x);
            const unsigned long long w1d = dup2(wp.y);
            const ulonglong2* row = (const ulonglong2*)(s_hT + k * CC + ph * 16);
#pragma unroll
            for (int q = 0; q < 4; q++) {
                const ulonglong2 h2 = row[q];
                a2[4 * q + 0] = fma2(h2.x, w0,  a2[4 * q + 0]);
                a2[4 * q + 1] = fma2(h2.x, w1d, a2[4 * q + 1]);
                a2[4 * q + 2] = fma2(h2.y, w0,  a2[4 * q + 2]);
                a2[4 * q + 3] = fma2(h2.y, w1d, a2[4 * q + 3]);
            }
        }
        const float b20 = fb2[d0], b21 = fb2[d1];
#pragma unroll
        for (int q = 0; q < 4; q++) {
            const int cb = ph * 16 + 4 * q;
            float lo, hi;
            unpack2(a2[4 * q + 0], lo, hi);
            s_feat[d0 * FS + cb]     = fmaxf(lo + b20, 0.f);
            s_feat[d0 * FS + cb + 1] = fmaxf(hi + b20, 0.f);
            unpack2(a2[4 * q + 1], lo, hi);
            s_feat[d1 * FS + cb]     = fmaxf(lo + b21, 0.f);
            s_feat[d1 * FS + cb + 1] = fmaxf(hi + b21, 0.f);
            unpack2(a2[4 * q + 2], lo, hi);
            s_feat[d0 * FS + cb + 2] = fmaxf(lo + b20, 0.f);
            s_feat[d0 * FS + cb + 3] = fmaxf(hi + b20, 0.f);
            unpack2(a2[4 * q + 3], lo, hi);
            s_feat[d1 * FS + cb + 2] = fmaxf(lo + b21, 0.f);
            s_feat[d1 * FS + cb + 3] = fmaxf(hi + b21, 0.f);
        }
    }
    __syncthreads();

    const int j0 = tid, j1 = tid + 128;
    unsigned long long acc[32];   // [4q+0]=j0/c(4q,4q+1) [4q+1]=j1/same
                                  // [4q+2]=j0/c(4q+2,4q+3) [4q+3]=j1/same ... x2 (q 0..7)

    // actor layer 1 over 128 candidate-feature rows (pooled part in g_pproj)
#pragma unroll
    for (int p = 0; p < 32; p++) acc[p] = 0ull;
#pragma unroll 2
    for (int i = 0; i < ND; i++) {
        const unsigned long long w0 = dup2(__ldg(aw1 + i * HA + j0));
        const unsigned long long w1d = dup2(__ldg(aw1 + i * HA + j1));
        const ulonglong2* row = (const ulonglong2*)(s_feat + i * FS);
#pragma unroll
        for (int q = 0; q < 8; q++) {
            const ulonglong2 f2 = row[q];
            acc[4 * q + 0] = fma2(f2.x, w0,  acc[4 * q + 0]);
            acc[4 * q + 1] = fma2(f2.x, w1d, acc[4 * q + 1]);
            acc[4 * q + 2] = fma2(f2.y, w0,  acc[4 * q + 2]);
            acc[4 * q + 3] = fma2(f2.y, w1d, acc[4 * q + 3]);
        }
    }
    {
        const float bj0 = ab1[j0] + g_pproj[b][j0];
        const float bj1 = ab1[j1] + g_pproj[b][j1];
#pragma unroll
        for (int q = 0; q < 8; q++) {
            float lo, hi;
            const int cb = 4 * q;
            unpack2(acc[4 * q + 0], lo, hi);
            s_mid[j0 * MS + cb]     = tanhf(lo + bj0);
            s_mid[j0 * MS + cb + 1] = tanhf(hi + bj0);
            unpack2(acc[4 * q + 1], lo, hi);
            s_mid[j1 * MS + cb]     = tanhf(lo + bj1);
            s_mid[j1 * MS + cb + 1] = tanhf(hi + bj1);
            unpack2(acc[4 * q + 2], lo, hi);
            s_mid[j0 * MS + cb + 2] = tanhf(lo + bj0);
            s_mid[j0 * MS + cb + 3] = tanhf(hi + bj0);
            unpack2(acc[4 * q + 3], lo, hi);
            s_mid[j1 * MS + cb + 2] = tanhf(lo + bj1);
            s_mid[j1 * MS + cb + 3] = tanhf(hi + bj1);
        }
    }
    __syncthreads();

    // actor layer 2: 256 -> 256
#pragma unroll
    for (int p = 0; p < 32; p++) acc[p] = 0ull;
#pragma unroll 2
    for (int i = 0; i < HA; i++) {
        const unsigned long long w0 = dup2(__ldg(aw2 + i * HA + j0));
        const unsigned long long w1d = dup2(__ldg(aw2 + i * HA + j1));
        const ulonglong2* row = (const ulonglong2*)(s_mid + i * MS);
#pragma unroll
        for (int q = 0; q < 8; q++) {
            const ulonglong2 f2 = row[q];
            acc[4 * q + 0] = fma2(f2.x, w0,  acc[4 * q + 0]);
            acc[4 * q + 1] = fma2(f2.x, w1d, acc[4 * q + 1]);
            acc[4 * q + 2] = fma2(f2.y, w0,  acc[4 * q + 2]);
            acc[4 * q + 3] = fma2(f2.y, w1d, acc[4 * q + 3]);
        }
    }

    // layer 3: tanh, weight by aw3, reduce over j (2 per thread, then 32 lanes,
    // then 4 warps)
    {
        const float bj0 = ab2[j0], bj1 = ab2[j1];
        const float w30 = aw3[j0], w31 = aw3[j1];
        float vc[CC];
#pragma unroll
        for (int q = 0; q < 8; q++) {
            float lo, hi;
            const int cb = 4 * q;
            float t0lo, t0hi, t2lo, t2hi;   // j0 contributions
            unpack2(acc[4 * q + 0], t0lo, t0hi);
            unpack2(acc[4 * q + 2], t2lo, t2hi);
            float u0lo, u0hi, u2lo, u2hi;   // j1 contributions
            unpack2(acc[4 * q + 1], u0lo, u0hi);
            unpack2(acc[4 * q + 3], u2lo, u2hi);
            vc[cb]     = tanhf(t0lo + bj0) * w30 + tanhf(u0lo + bj1) * w31;
            vc[cb + 1] = tanhf(t0hi + bj0) * w30 + tanhf(u0hi + bj1) * w31;
            vc[cb + 2] = tanhf(t2lo + bj0) * w30 + tanhf(u2lo + bj1) * w31;
            vc[cb + 3] = tanhf(t2hi + bj0) * w30 + tanhf(u2hi + bj1) * w31;
            (void)lo; (void)hi;
        }
        const int lane = tid & 31, warp = tid >> 5;
#pragma unroll
        for (int c = 0; c < CC; c++) {
            float v = vc[c];
            v += __shfl_xor_sync(0xffffffffu, v, 16);
            v += __shfl_xor_sync(0xffffffffu, v, 8);
            v += __shfl_xor_sync(0xffffffffu, v, 4);
            v += __shfl_xor_sync(0xffffffffu, v, 2);
            v += __shfl_xor_sync(0xffffffffu, v, 1);
            if (lane == 0) s_red[warp * CC + c] = v;
        }
    }
    __syncthreads();
    if (tid < CC) {
        float s = ab3[0];
#pragma unroll
        for (int w = 0; w < 4; w++) s += s_red[w * CC + tid];
        if (tid < nvalid) g_scores[b][c0 + tid] = s;
    }
}

// ---------------------------------------------------------------------------
// K3: critic MLP on pooled feature + masked softmax over candidates.
// ---------------------------------------------------------------------------
__global__ __launch_bounds__(256) void k_final(
    const unsigned char* __restrict__ mask,
    const float* __restrict__ cw1, const float* __restrict__ cb1,
    const float* __restrict__ cw2, const float* __restrict__ cb2,
    const float* __restrict__ cw3, const float* __restrict__ cb3,
    float* __restrict__ out)
{
    __shared__ float s_in[HA];
    __shared__ float s_hid[HA];
    __shared__ float s_r[8];
    __shared__ float s_b0, s_b1v;

    const int tid = threadIdx.x, b = blockIdx.x;
    const int lane = tid & 31, warp = tid >> 5;

    // --- critic ---
    s_in[tid] = g_pooled[b][tid];
    __syncthreads();
    float acc = cb1[tid];
    for (int i = 0; i < HA; i++) acc = fmaf(s_in[i], cw1[i * HA + tid], acc);
    s_hid[tid] = tanhf(acc);
    __syncthreads();
    acc = cb2[tid];
    for (int i = 0; i < HA; i++) acc = fmaf(s_hid[i], cw2[i * HA + tid], acc);
    {
        float p = tanhf(acc) * cw3[tid];
        p += __shfl_xor_sync(0xffffffffu, p, 16);
        p += __shfl_xor_sync(0xffffffffu, p, 8);
        p += __shfl_xor_sync(0xffffffffu, p, 4);
        p += __shfl_xor_sync(0xffffffffu, p, 2);
        p += __shfl_xor_sync(0xffffffffu, p, 1);
        if (lane == 0) s_r[warp] = p;
    }
    __syncthreads();
    if (tid == 0) {
        float v = cb3[0];
#pragma unroll
        for (int w = 0; w < 8; w++) v += s_r[w];
        out[BATCH * NC + b] = v;
    }

    // --- masked softmax over candidates ---
    const int c = tid;
    bool valid = false;
    float s = -FLT_MAX;
    if (c < NC) {
        const int mi = b * NC + c;
        const int mv = g_mask_i32 ? ((const int*)mask)[mi] : (int)mask[mi];
        valid = (mv != 0);
        if (valid) s = g_scores[b][c];
    }
    float m = s;
    m = fmaxf(m, __shfl_xor_sync(0xffffffffu, m, 16));
    m = fmaxf(m, __shfl_xor_sync(0xffffffffu, m, 8));
    m = fmaxf(m, __shfl_xor_sync(0xffffffffu, m, 4));
    m = fmaxf(m, __shfl_xor_sync(0xffffffffu, m, 2));
    m = fmaxf(m, __shfl_xor_sync(0xffffffffu, m, 1));
    __syncthreads();
    if (lane == 0) s_r[warp] = m;
    __syncthreads();
    if (warp == 0) {
        float t = (lane < 8) ? s_r[lane] : -FLT_MAX;
        t = fmaxf(t, __shfl_xor_sync(0xffffffffu, t, 4));
        t = fmaxf(t, __shfl_xor_sync(0xffffffffu, t, 2));
        t = fmaxf(t, __shfl_xor_sync(0xffffffffu, t, 1));
        if (lane == 0) s_b0 = t;
    }
    __syncthreads();
    const float mx = s_b0;
    const float e = valid ? expf(s - mx) : 0.f;
    float se = e;
    se += __shfl_xor_sync(0xffffffffu, se, 16);
    se += __shfl_xor_sync(0xffffffffu, se, 8);
    se += __shfl_xor_sync(0xffffffffu, se, 4);
    se += __shfl_xor_sync(0xffffffffu, se, 2);
    se += __shfl_xor_sync(0xffffffffu, se, 1);
    __syncthreads();
    if (lane == 0) s_r[warp] = se;
    __syncthreads();
    if (warp == 0) {
        float t = (lane < 8) ? s_r[lane] : 0.f;
        t += __shfl_xor_sync(0xffffffffu, t, 4);
        t += __shfl_xor_sync(0xffffffffu, t, 2);
        t += __shfl_xor_sync(0xffffffffu, t, 1);
        if (lane == 0) s_b1v = t;
    }
    __syncthreads();
    if (c < NC) out[b * NC + c] = e / s_b1v;
}

// ---------------------------------------------------------------------------
extern "C" void kernel_launch(void* const* d_in, const int* in_sizes, int n_in,
                              void* d_out, int out_size)
{
    const float* x    = (const float*)d_in[0];
    const int*   cand = (const int*)d_in[1];
    const unsigned char* mask = (const unsigned char*)d_in[2];
    const float* fw1 = (const float*)d_in[3];
    const float* fb1 = (const float*)d_in[4];
    const float* fw2 = (const float*)d_in[5];
    const float* fb2 = (const float*)d_in[6];
    const float* aw1 = (const float*)d_in[7];
    const float* ab1 = (const float*)d_in[8];
    const float* aw2 = (const float*)d_in[9];
    const float* ab2 = (const float*)d_in[10];
    const float* aw3 = (const float*)d_in[11];
    const float* ab3 = (const float*)d_in[12];
    const float* cw1 = (const float*)d_in[13];
    const float* cb1 = (const float*)d_in[14];
    const float* cw2 = (const float*)d_in[15];
    const float* cb2 = (const float*)d_in[16];
    const float* cw3 = (const float*)d_in[17];
    const float* cb3 = (const float*)d_in[18];
    float* out = (float*)d_out;

    const int smem_actor =
        (ND * FS + HA * MS + H * CC + CC * 3 + H * 4 + 4 * CC) * (int)sizeof(float);
    cudaFuncSetAttribute(k_actor, cudaFuncAttributeMaxDynamicSharedMemorySize,
                         smem_actor);

    k_sniff<<<1, 32>>>(mask);
    k_featpool<<<dim3(NB, BATCH), 128>>>(x, fw1, fb1, fw2, fb2);
    k_pool<<<BATCH, HA>>>(aw1);
    k_actor<<<dim3(NCHUNK, BATCH), 128, smem_actor>>>(
        x, cand, fw1, fb1, fw2, fb2, aw1, ab1, aw2, ab2, aw3, ab3);
    k_final<<<BATCH, 256>>>(mask, cw1, cb1, cw2, cb2, cw3, cb3, out);
}